// round 7
// baseline (speedup 1.0000x reference)
#include <cuda_runtime.h>
#include <math.h>

#define Dk 512
#define Ek 8
#define Hk 128
#define MAXN 32768
#define CAPSTRIDE 5120
#define NBMAX (MAXN/256)

// ---------------- device scratch ----------------
__device__ int   g_top[MAXN];
__device__ float g_conf[MAXN];
__device__ int   g_kcnt[MAXN];
__device__ int   g_boff[NBMAX*Ek];
__device__ int   g_list[Ek*CAPSTRIDE];
__device__ int   g_Me[Ek];
__device__ int   g_tile;

// ---------------- tf32 mma + 3xTF32 split ----------------
__device__ __forceinline__ void mma8(float* c, const uint4& a, const uint2& b) {
    asm volatile(
        "mma.sync.aligned.m16n8k8.row.col.f32.tf32.tf32.f32 "
        "{%0,%1,%2,%3}, {%4,%5,%6,%7}, {%8,%9}, {%0,%1,%2,%3};"
        : "+f"(c[0]), "+f"(c[1]), "+f"(c[2]), "+f"(c[3])
        : "r"(a.x), "r"(a.y), "r"(a.z), "r"(a.w), "r"(b.x), "r"(b.y));
}
__device__ __forceinline__ void spl(unsigned v, unsigned& hi, unsigned& lo) {
    float f = __uint_as_float(v), h;
    asm("cvt.rna.tf32.f32 %0, %1;" : "=r"(hi) : "f"(f));
    h = __uint_as_float(hi);
    asm("cvt.rna.tf32.f32 %0, %1;" : "=r"(lo) : "f"(f - h));
}
__device__ __forceinline__ void split4(const uint4& a, uint4& h, uint4& l) {
    spl(a.x, h.x, l.x); spl(a.y, h.y, l.y); spl(a.z, h.z, l.z); spl(a.w, h.w, l.w);
}
__device__ __forceinline__ void split2(const uint2& a, uint2& h, uint2& l) {
    spl(a.x, h.x, l.x); spl(a.y, h.y, l.y);
}

// ---------------- router ----------------
__global__ void router_kernel(const float* __restrict__ x,
                              const float* __restrict__ Wr,
                              const float* __restrict__ br, int N)
{
    __shared__ float sWr[Dk*Ek];
    int t = threadIdx.x;
    for (int i = t; i < Dk*Ek/4; i += 256)
        ((float4*)sWr)[i] = ((const float4*)Wr)[i];
    __syncthreads();

    int tok  = blockIdx.x*8 + (t >> 5);
    int lane = t & 31;
    if (tok >= N) return;
    const float* xr = x + (size_t)tok*Dk;

    float acc[Ek];
#pragma unroll
    for (int e = 0; e < Ek; e++) acc[e] = 0.f;

    for (int c = lane; c < Dk/4; c += 32) {
        float4 v = *(const float4*)(xr + c*4);
        const float* w = sWr + c*4*Ek;
        float xv[4] = {v.x, v.y, v.z, v.w};
#pragma unroll
        for (int kk = 0; kk < 4; kk++)
#pragma unroll
            for (int e = 0; e < Ek; e++)
                acc[e] = fmaf(xv[kk], w[kk*Ek + e], acc[e]);
    }
#pragma unroll
    for (int off = 16; off; off >>= 1)
#pragma unroll
        for (int e = 0; e < Ek; e++)
            acc[e] += __shfl_xor_sync(0xffffffffu, acc[e], off);

    if (lane == 0) {
        float v1 = -3e38f, v2 = -3e38f; int i1 = 0, i2 = 1;
#pragma unroll
        for (int e = 0; e < Ek; e++) {
            float v = acc[e] + br[e];
            if (v > v1)      { v2 = v1; i2 = i1; v1 = v; i1 = e; }
            else if (v > v2) { v2 = v;  i2 = e; }
        }
        g_top[tok]  = i1 | (i2 << 4);
        g_conf[tok] = v1;
        g_kcnt[tok] = 0;
    }
}

// ---------------- scanA: counts + prefix + stats (single block) ----------
__global__ void scanA_kernel(int NB, int N, int cap, float* tail)
{
    __shared__ int   cnt[NBMAX*Ek];
    __shared__ float csum[32];
    __shared__ int   tot[Ek];
    int t = threadIdx.x, lane = t & 31, w = t >> 5;

    float cpart = 0.f;
    for (int c = w; c < NB; c += 32) {
        int cnts[Ek];
#pragma unroll
        for (int e = 0; e < Ek; e++) cnts[e] = 0;
#pragma unroll
        for (int g = 0; g < 8; g++) {
            int idx = c*256 + g*32 + lane;
            int pk = -1; float cf = 0.f;
            if (idx < N) { pk = g_top[idx]; cf = g_conf[idx]; }
            cpart += cf;
#pragma unroll
            for (int e = 0; e < Ek; e++) {
                bool m = (pk >= 0) && (((pk & 15) == e) || (((pk >> 4) & 15) == e));
                cnts[e] += __popc(__ballot_sync(0xffffffffu, m));
            }
        }
        if (lane < Ek) cnt[c*Ek + lane] = cnts[lane];
    }
#pragma unroll
    for (int off = 16; off; off >>= 1)
        cpart += __shfl_xor_sync(0xffffffffu, cpart, off);
    if (lane == 0) csum[w] = cpart;
    __syncthreads();

    if (t < Ek) {
        int run = 0;
        for (int c = 0; c < NB; c++) { g_boff[c*Ek + t] = run; run += cnt[c*Ek + t]; }
        tot[t] = run;
        g_Me[t] = run < cap ? run : cap;
    }
    if (t == 0) g_tile = 0;
    __syncthreads();
    if (t == 0) {
        float s = 0.f, load[Ek];
        for (int i = 0; i < Ek; i++) {
            int l = tot[i] < cap ? tot[i] : cap;
            load[i] = (float)l; s += load[i];
        }
        float inv = 1.f / (s + 1e-8f);
        float loss = 0.f;
        for (int i = 0; i < Ek; i++) {
            float d = load[i] * inv;
            loss += d * logf(d + 1e-8f);
            tail[1 + i] = d;
        }
        tail[0] = loss;
        float cs = 0.f;
        for (int i = 0; i < 32; i++) cs += csum[i];
        tail[9] = cs / (float)N;
    }
}

// ---------------- scan3: compacted lists + keep counts ----------------
__global__ void scan3_kernel(int N, int cap)
{
    __shared__ int spk[256];
    int t = threadIdx.x, b = blockIdx.x;
    int base = b*256;
    int lim = N - base; if (lim > 256) lim = 256;
    spk[t] = (t < lim) ? g_top[base + t] : -1;
    __syncthreads();
    int e = t >> 5, lane = t & 31;
    int run = g_boff[b*Ek + e];
#pragma unroll
    for (int r = 0; r < 8; r++) {
        int i = r*32 + lane;
        int pk = spk[i];
        bool m = (pk >= 0) && (((pk & 15) == e) || (((pk >> 4) & 15) == e));
        unsigned bal = __ballot_sync(0xffffffffu, m);
        if (m) {
            int idx = run + __popc(bal & ((1u << lane) - 1u));
            if (idx < cap) {
                g_list[e*CAPSTRIDE + idx] = base + i;
                atomicAdd(&g_kcnt[base + i], 1);
            }
        }
        run += __popc(bal);
    }
}

// ---------------- persistent 3xTF32 mma FFN ----------------
// 256 thr (8 warps, 2x4 grid, warp tile 64x32), MT=128 token tiles.
#define MT 128
#define AP_OFF   0        // 2 x 4096 floats (X chunks, A-frag packed)
#define BP_OFF   32768    // 2 x 4096 floats (W chunks, B-frag packed)
#define HP_OFF   65536    // 16384 floats (H, A-frag packed)
#define ROWS_OFF 131072
#define KEPT_OFF 131584
#define SB1_OFF  132096
#define SB2_OFF  132608
#define SMEM_BYTES 134656

__global__ void __launch_bounds__(256, 1)
ffn_mma(const float* __restrict__ x,  const float* __restrict__ W1,
        const float* __restrict__ b1, const float* __restrict__ W2,
        const float* __restrict__ b2, float* __restrict__ out,
        int ntiles, int tilesPerE)
{
    extern __shared__ char smem[];
    float* AP   = (float*)(smem + AP_OFF);
    float* BP   = (float*)(smem + BP_OFF);
    float* HP   = (float*)(smem + HP_OFF);
    int*   rows = (int*)  (smem + ROWS_OFF);
    int*   kept = (int*)  (smem + KEPT_OFF);
    float* sB1  = (float*)(smem + SB1_OFF);
    float* sB2  = (float*)(smem + SB2_OFF);
    __shared__ int stile;

    int tid  = threadIdx.x;
    int lane = tid & 31;
    int w    = tid >> 5;
    int wr   = w >> 2, wc = w & 3;

    // staging maps
    int xm = tid >> 1, xq = (tid & 1) * 16;          // X: token row, k-halves
    int wk = tid >> 5, wn = (tid & 31) * 4;          // W: k row, 4 n cols
    int xmt = xm >> 4, xr_ = xm & 15;
    int xlb = (xr_ & 7) * 4, xrh = (xr_ >= 8) ? 1 : 0;
    int wnt = wn >> 3, wnl = wn & 7;

    for (;;) {
        __syncthreads();
        if (tid == 0) stile = atomicAdd(&g_tile, 1);
        __syncthreads();
        int t = stile;
        if (t >= ntiles) break;
        int e  = t / tilesPerE;
        int m0 = (t - e*tilesPerE) * MT;
        int Me = g_Me[e];
        if (m0 >= Me) continue;

        if (tid < 128) {
            int m = m0 + tid;
            int mm = m < Me ? m : (Me - 1);
            int tok = g_list[e*CAPSTRIDE + mm];
            rows[tid] = tok;
            kept[tid] = g_kcnt[tok];
            sB1[tid]  = b1[e*Hk + tid];
        }
        sB2[tid]       = b2[e*Dk + tid];
        sB2[tid + 256] = b2[e*Dk + 256 + tid];
        __syncthreads();

        const float* W1e = W1 + (size_t)e*Dk*Hk;
        const float* W2e = W2 + (size_t)e*Hk*Dk;
        const float* xrow = x + (size_t)rows[xm]*Dk + xq;

        float acc[4][4][4];
#pragma unroll
        for (int i = 0; i < 4; i++)
#pragma unroll
            for (int j = 0; j < 4; j++)
#pragma unroll
                for (int q = 0; q < 4; q++) acc[i][j][q] = 0.f;

        // ================= GEMM1: 16 chunks of k=32 =================
        {   // prologue: stage chunk 0 into buf 0
            float4 xv[4], wv[4];
#pragma unroll
            for (int q = 0; q < 4; q++) xv[q] = *(const float4*)(xrow + q*4);
#pragma unroll
            for (int q = 0; q < 4; q++) wv[q] = *(const float4*)(W1e + (size_t)(wk + 8*q)*Hk + wn);
#pragma unroll
            for (int q = 0; q < 4; q++) {
                int kk = xq + q*4;
                int kt = kk >> 3, ch = ((kk & 7) >= 4) ? 2 : 0;
                float* dst = AP + ((kt*8 + xmt)*32 + xlb)*4 + xrh + ch;
                dst[0] = xv[q].x; dst[4] = xv[q].y; dst[8] = xv[q].z; dst[12] = xv[q].w;
            }
#pragma unroll
            for (int q = 0; q < 4; q++) {
                int reg = wk >> 2;
                float* dst = BP + ((q*16 + wnt)*32 + wnl*4 + (wk & 3))*2 + reg;
                dst[0] = wv[q].x; dst[8] = wv[q].y; dst[16] = wv[q].z; dst[24] = wv[q].w;
            }
            __syncthreads();
        }

        for (int c = 0; c < 16; c++) {
            int b = c & 1;
            float4 xv[4], wv[4];
            if (c + 1 < 16) {
#pragma unroll
                for (int q = 0; q < 4; q++) xv[q] = *(const float4*)(xrow + (c+1)*32 + q*4);
#pragma unroll
                for (int q = 0; q < 4; q++) wv[q] = *(const float4*)(W1e + (size_t)((c+1)*32 + wk + 8*q)*Hk + wn);
            }
            const uint4* A4 = (const uint4*)(AP + b*4096);
            const uint2* B2 = (const uint2*)(BP + b*4096);
#pragma unroll
            for (int kt = 0; kt < 4; kt++) {
                uint4 ah[4], al[4]; uint2 bh[4], bl[4];
#pragma unroll
                for (int i = 0; i < 4; i++) {
                    uint4 af = A4[(kt*8 + wr*4 + i)*32 + lane];
                    split4(af, ah[i], al[i]);
                }
#pragma unroll
                for (int j = 0; j < 4; j++) {
                    uint2 bf = B2[(kt*16 + wc*4 + j)*32 + lane];
                    split2(bf, bh[j], bl[j]);
                }
#pragma unroll
                for (int i = 0; i < 4; i++)
#pragma unroll
                    for (int j = 0; j < 4; j++) {
                        mma8(acc[i][j], ah[i], bh[j]);
                        mma8(acc[i][j], al[i], bh[j]);
                        mma8(acc[i][j], ah[i], bl[j]);
                    }
            }
            if (c + 1 < 16) {
                int nb = b ^ 1;
#pragma unroll
                for (int q = 0; q < 4; q++) {
                    int kk = xq + q*4;
                    int kt = kk >> 3, ch = ((kk & 7) >= 4) ? 2 : 0;
                    float* dst = AP + nb*4096 + ((kt*8 + xmt)*32 + xlb)*4 + xrh + ch;
                    dst[0] = xv[q].x; dst[4] = xv[q].y; dst[8] = xv[q].z; dst[12] = xv[q].w;
                }
#pragma unroll
                for (int q = 0; q < 4; q++) {
                    int reg = wk >> 2;
                    float* dst = BP + nb*4096 + ((q*16 + wnt)*32 + wnl*4 + (wk & 3))*2 + reg;
                    dst[0] = wv[q].x; dst[8] = wv[q].y; dst[16] = wv[q].z; dst[24] = wv[q].w;
                }
            }
            __syncthreads();
        }

        // ===== H epilogue: relu(acc + b1) -> HP (A-frag packed) =====
        {
            int r = lane >> 2, cq = 2*(lane & 3);
#pragma unroll
            for (int i = 0; i < 4; i++) {
                int mt = wr*4 + i;
#pragma unroll
                for (int j = 0; j < 4; j++) {
                    int n0 = wc*32 + j*8;
#pragma unroll
                    for (int q = 0; q < 4; q++) {
                        int rr = r + ((q >= 2) ? 8 : 0);
                        int h  = n0 + cq + (q & 1);
                        float v = fmaxf(acc[i][j][q] + sB1[h], 0.f);
                        int kt = h >> 3, c2 = h & 7;
                        HP[((kt*8 + mt)*32 + (rr & 7)*4 + (c2 & 3))*4
                           + ((rr >= 8) ? 1 : 0) + ((c2 >= 4) ? 2 : 0)] = v;
                    }
                }
            }
        }

        // ===== GEMM2 prologue: stage W2 stage-0 into buf 0 =====
        {
#pragma unroll
            for (int q = 0; q < 4; q++) {
                float4 wv = *(const float4*)(W2e + (size_t)(wk + 8*q)*Dk + wn);
                int reg = wk >> 2;
                float* dst = BP + ((q*16 + wnt)*32 + wnl*4 + (wk & 3))*2 + reg;
                dst[0] = wv.x; dst[8] = wv.y; dst[16] = wv.z; dst[24] = wv.w;
            }
            __syncthreads();  // also publishes HP
        }

        // ================= GEMM2: 4 n-chunks x 4 k-chunks =================
        const uint4* H4 = (const uint4*)HP;
        for (int s = 0; s < 16; s++) {
            int b = s & 1;
            int nc = s >> 2, kc = s & 3;
            if (kc == 0) {
#pragma unroll
                for (int i = 0; i < 4; i++)
#pragma unroll
                    for (int j = 0; j < 4; j++)
#pragma unroll
                        for (int q = 0; q < 4; q++) acc[i][j][q] = 0.f;
            }
            float4 wv[4];
            if (s + 1 < 16) {
                int nnc = (s+1) >> 2, nkc = (s+1) & 3;
#pragma unroll
                for (int q = 0; q < 4; q++)
                    wv[q] = *(const float4*)(W2e + (size_t)(nkc*32 + wk + 8*q)*Dk + nnc*128 + wn);
            }
            const uint2* B2 = (const uint2*)(BP + b*4096);
#pragma unroll
            for (int kt = 0; kt < 4; kt++) {
                uint4 ah[4], al[4]; uint2 bh[4], bl[4];
#pragma unroll
                for (int i = 0; i < 4; i++) {
                    uint4 af = H4[((kc*4 + kt)*8 + wr*4 + i)*32 + lane];
                    split4(af, ah[i], al[i]);
                }
#pragma unroll
                for (int j = 0; j < 4; j++) {
                    uint2 bf = B2[(kt*16 + wc*4 + j)*32 + lane];
                    split2(bf, bh[j], bl[j]);
                }
#pragma unroll
                for (int i = 0; i < 4; i++)
#pragma unroll
                    for (int j = 0; j < 4; j++) {
                        mma8(acc[i][j], ah[i], bh[j]);
                        mma8(acc[i][j], al[i], bh[j]);
                        mma8(acc[i][j], ah[i], bl[j]);
                    }
            }
            if (s + 1 < 16) {
                int nb = b ^ 1;
#pragma unroll
                for (int q = 0; q < 4; q++) {
                    int reg = wk >> 2;
                    float* dst = BP + nb*4096 + ((q*16 + wnt)*32 + wnl*4 + (wk & 3))*2 + reg;
                    dst[0] = wv[q].x; dst[8] = wv[q].y; dst[16] = wv[q].z; dst[24] = wv[q].w;
                }
            }
            __syncthreads();

            if (kc == 3) {  // output epilogue for this n-chunk
                int r = lane >> 2, cq = 2*(lane & 3);
#pragma unroll
                for (int i = 0; i < 4; i++) {
                    int mA = (wr*4 + i)*16 + r;
                    int mB = mA + 8;
                    bool okA = (m0 + mA) < Me, okB = (m0 + mB) < Me;
                    int kA = kept[mA], kB = kept[mB];
                    float* oA = out + (size_t)rows[mA]*Dk;
                    float* oB = out + (size_t)rows[mB]*Dk;
#pragma unroll
                    for (int j = 0; j < 4; j++) {
                        int col = nc*128 + wc*32 + j*8 + cq;
                        float bA = sB2[col], bB = sB2[col + 1];
                        if (okA) {
                            float v0 = acc[i][j][0] + bA, v1 = acc[i][j][1] + bB;
                            if (kA == 1) *(float2*)(oA + col) = make_float2(v0, v1);
                            else { atomicAdd(oA + col, v0); atomicAdd(oA + col + 1, v1); }
                        }
                        if (okB) {
                            float v2 = acc[i][j][2] + bA, v3 = acc[i][j][3] + bB;
                            if (kB == 1) *(float2*)(oB + col) = make_float2(v2, v3);
                            else { atomicAdd(oB + col, v2); atomicAdd(oB + col + 1, v3); }
                        }
                    }
                }
            }
        }
    }
}

// ---------------- launch ----------------
extern "C" void kernel_launch(void* const* d_in, const int* in_sizes, int n_in,
                              void* d_out, int out_size)
{
    const float* x  = (const float*)d_in[0];
    const float* Wr = (const float*)d_in[1];
    const float* br = (const float*)d_in[2];
    const float* W1 = (const float*)d_in[3];
    const float* b1 = (const float*)d_in[4];
    const float* W2 = (const float*)d_in[5];
    const float* b2 = (const float*)d_in[6];
    float* out = (float*)d_out;

    int N = in_sizes[0] / Dk;
    if (N > MAXN) N = MAXN;
    int cap = (int)(1.25f * ((float)N / (float)Ek));
    if (cap > CAPSTRIDE) cap = CAPSTRIDE;
    int NB = (N + 255) / 256;

    static int smem_set = 0;
    if (!smem_set) {
        cudaFuncSetAttribute(ffn_mma, cudaFuncAttributeMaxDynamicSharedMemorySize, SMEM_BYTES);
        smem_set = 1;
    }

    cudaMemsetAsync(d_out, 0, (size_t)out_size * sizeof(float), 0);
    router_kernel<<<(N + 7) / 8, 256>>>(x, Wr, br, N);
    scanA_kernel<<<1, 1024>>>(NB, N, cap, out + (size_t)N * Dk);
    scan3_kernel<<<NB, 256>>>(N, cap);

    int tilesPerE = (cap + MT - 1) / MT;
    int ntiles = tilesPerE * Ek;
    ffn_mma<<<148, 256, SMEM_BYTES>>>(x, W1, b1, W2, b2, out, ntiles, tilesPerE);
}